// round 14
// baseline (speedup 1.0000x reference)
#include <cuda_runtime.h>

// Problem constants
#define DD 300
#define LL 128
#define BC 2048                  // B*C = 32*64
#define THREADS 64               // 2 warps: same 32 row-pairs, split over D
#define DHALF 150
#define UB 6                     // 150 = 6 * 25
#define NBLOCKS (BC * 2)         // each block covers half a slab's L (64 rows)

__global__ void __launch_bounds__(THREADS, 16)
hcmp_kernel(const float* __restrict__ x,
            const float* __restrict__ y,
            float* __restrict__ out)
{
    const int slab  = blockIdx.x >> 1;            // (b*C + c)
    const int lbase = (blockIdx.x & 1) * 64;      // which half of L
    const int lane  = threadIdx.x & 31;
    const int half  = threadIdx.x >> 5;           // 0: d[0,150), 1: d[150,300)
    const int l0    = lbase + lane * 2;           // even l, this thread's 2 rows

    // float2 view: element (slab, d, l0..l0+1); d-stride = L/2 = 64 float2s.
    const float2* __restrict__ xp =
        reinterpret_cast<const float2*>(x + (size_t)slab * (DD * LL) + l0)
        + (size_t)half * DHALF * (LL / 2);
    const float2* __restrict__ yp =
        reinterpret_cast<const float2*>(y + (size_t)slab * (DD * LL) + l0)
        + (size_t)half * DHALF * (LL / 2);

    float sxx0 = 0.f, syy0 = 0.f, sxy0 = 0.f, sl10 = 0.f, sdd0 = 0.f;
    float sxx1 = 0.f, syy1 = 0.f, sxy1 = 0.f, sl11 = 0.f, sdd1 = 0.f;

    for (int d = 0; d < DHALF; d += UB) {
        float2 xa[UB], ya[UB];
        #pragma unroll
        for (int u = 0; u < UB; u++)
            xa[u] = __ldcs(xp + (d + u) * (LL / 2));
        #pragma unroll
        for (int u = 0; u < UB; u++)
            ya[u] = __ldcs(yp + (d + u) * (LL / 2));

        #pragma unroll
        for (int u = 0; u < UB; u++) {
            float xv0 = xa[u].x, yv0 = ya[u].x;
            float df0 = xv0 - yv0;
            sxx0 = fmaf(xv0, xv0, sxx0);
            syy0 = fmaf(yv0, yv0, syy0);
            sxy0 = fmaf(xv0, yv0, sxy0);
            sdd0 = fmaf(df0, df0, sdd0);
            sl10 += fabsf(df0);

            float xv1 = xa[u].y, yv1 = ya[u].y;
            float df1 = xv1 - yv1;
            sxx1 = fmaf(xv1, xv1, sxx1);
            syy1 = fmaf(yv1, yv1, syy1);
            sxy1 = fmaf(xv1, yv1, sxy1);
            sdd1 = fmaf(df1, df1, sdd1);
            sl11 += fabsf(df1);
        }
    }

    // Combine the two D-halves: warp 1 -> smem, warp 0 adds + epilogue.
    // Stride 11 (coprime with 32) => conflict-free.
    __shared__ float red[32 * 11];
    if (half == 1) {
        float* r = red + lane * 11;
        r[0] = sxx0; r[1] = syy0; r[2] = sxy0; r[3] = sdd0; r[4] = sl10;
        r[5] = sxx1; r[6] = syy1; r[7] = sxy1; r[8] = sdd1; r[9] = sl11;
    }
    __syncthreads();
    if (half == 0) {
        const float* r = red + lane * 11;
        float txx0 = sxx0 + r[0], tyy0 = syy0 + r[1], txy0 = sxy0 + r[2];
        float tdd0 = sdd0 + r[3], tl10 = sl10 + r[4];
        float txx1 = sxx1 + r[5], tyy1 = syy1 + r[6], txy1 = sxy1 + r[7];
        float tdd1 = sdd1 + r[8], tl11 = sl11 + r[9];

        float nx0 = fmaxf(sqrtf(txx0), 1e-12f);
        float ny0 = fmaxf(sqrtf(tyy0), 1e-12f);
        float cos0 = txy0 / (nx0 * ny0);
        float sq0 = tdd0;
        if (sq0 < 1e-8f) sq0 += 1e-8f;   // revise_zero_data
        float l20 = sqrtf(sq0);

        float nx1 = fmaxf(sqrtf(txx1), 1e-12f);
        float ny1 = fmaxf(sqrtf(tyy1), 1e-12f);
        float cos1 = txy1 / (nx1 * ny1);
        float sq1 = tdd1;
        if (sq1 < 1e-8f) sq1 += 1e-8f;
        float l21 = sqrtf(sq1);

        // Output rows slab*128 + l0, l0+1 => 6 contiguous floats.
        float* o = out + ((size_t)slab * LL + l0) * 3;
        o[0] = cos0;
        o[1] = l20;
        o[2] = tl10;
        o[3] = cos1;
        o[4] = l21;
        o[5] = tl11;
    }
}

extern "C" void kernel_launch(void* const* d_in, const int* in_sizes, int n_in,
                              void* d_out, int out_size)
{
    const float* x = (const float*)d_in[0];
    const float* y = (const float*)d_in[1];
    float* out = (float*)d_out;

    dim3 grid(NBLOCKS);     // 4096 blocks
    dim3 block(THREADS);    // 64 threads = 2 warps
    hcmp_kernel<<<grid, block>>>(x, y, out);
}

// round 15
// speedup vs baseline: 1.0162x; 1.0162x over previous
#include <cuda_runtime.h>

// Problem constants
#define DD 300
#define LL 128
#define BC 2048                  // B*C = 32*64
#define THREADS 64               // 2 warps: same 32 row-pairs, split over D
#define DHALF 150
#define UB 6                     // 150 = 6 * 25
#define NBLOCKS (BC * 2)         // each block covers half a slab's L (64 rows)

__global__ void __launch_bounds__(THREADS, 16)
hcmp_kernel(const float* __restrict__ x,
            const float* __restrict__ y,
            float* __restrict__ out)
{
    const int slab  = blockIdx.x >> 1;            // (b*C + c)
    const int lbase = (blockIdx.x & 1) * 64;      // which half of L
    const int lane  = threadIdx.x & 31;
    const int half  = threadIdx.x >> 5;           // 0: d[0,150), 1: d[150,300)
    const int l0    = lbase + lane * 2;           // even l, this thread's 2 rows

    // float2 view: element (slab, d, l0..l0+1); d-stride = L/2 = 64 float2s.
    const float2* __restrict__ xp =
        reinterpret_cast<const float2*>(x + (size_t)slab * (DD * LL) + l0)
        + (size_t)half * DHALF * (LL / 2);
    const float2* __restrict__ yp =
        reinterpret_cast<const float2*>(y + (size_t)slab * (DD * LL) + l0)
        + (size_t)half * DHALF * (LL / 2);

    float sxx0 = 0.f, syy0 = 0.f, sxy0 = 0.f, sl10 = 0.f, sdd0 = 0.f;
    float sxx1 = 0.f, syy1 = 0.f, sxy1 = 0.f, sl11 = 0.f, sdd1 = 0.f;

    for (int d = 0; d < DHALF; d += UB) {
        float2 xa[UB], ya[UB];
        // Interleaved issue order: x/y pairs per d. Same addresses, same
        // batch depth — only the LDG stream alternation changes.
        #pragma unroll
        for (int u = 0; u < UB; u++) {
            xa[u] = __ldcs(xp + (d + u) * (LL / 2));
            ya[u] = __ldcs(yp + (d + u) * (LL / 2));
        }

        #pragma unroll
        for (int u = 0; u < UB; u++) {
            float xv0 = xa[u].x, yv0 = ya[u].x;
            float df0 = xv0 - yv0;
            sxx0 = fmaf(xv0, xv0, sxx0);
            syy0 = fmaf(yv0, yv0, syy0);
            sxy0 = fmaf(xv0, yv0, sxy0);
            sdd0 = fmaf(df0, df0, sdd0);
            sl10 += fabsf(df0);

            float xv1 = xa[u].y, yv1 = ya[u].y;
            float df1 = xv1 - yv1;
            sxx1 = fmaf(xv1, xv1, sxx1);
            syy1 = fmaf(yv1, yv1, syy1);
            sxy1 = fmaf(xv1, yv1, sxy1);
            sdd1 = fmaf(df1, df1, sdd1);
            sl11 += fabsf(df1);
        }
    }

    // Combine the two D-halves: warp 1 -> smem, warp 0 adds + epilogue.
    // Stride 11 (coprime with 32) => conflict-free.
    __shared__ float red[32 * 11];
    if (half == 1) {
        float* r = red + lane * 11;
        r[0] = sxx0; r[1] = syy0; r[2] = sxy0; r[3] = sdd0; r[4] = sl10;
        r[5] = sxx1; r[6] = syy1; r[7] = sxy1; r[8] = sdd1; r[9] = sl11;
    }
    __syncthreads();
    if (half == 0) {
        const float* r = red + lane * 11;
        float txx0 = sxx0 + r[0], tyy0 = syy0 + r[1], txy0 = sxy0 + r[2];
        float tdd0 = sdd0 + r[3], tl10 = sl10 + r[4];
        float txx1 = sxx1 + r[5], tyy1 = syy1 + r[6], txy1 = sxy1 + r[7];
        float tdd1 = sdd1 + r[8], tl11 = sl11 + r[9];

        float nx0 = fmaxf(sqrtf(txx0), 1e-12f);
        float ny0 = fmaxf(sqrtf(tyy0), 1e-12f);
        float cos0 = txy0 / (nx0 * ny0);
        float sq0 = tdd0;
        if (sq0 < 1e-8f) sq0 += 1e-8f;   // revise_zero_data
        float l20 = sqrtf(sq0);

        float nx1 = fmaxf(sqrtf(txx1), 1e-12f);
        float ny1 = fmaxf(sqrtf(tyy1), 1e-12f);
        float cos1 = txy1 / (nx1 * ny1);
        float sq1 = tdd1;
        if (sq1 < 1e-8f) sq1 += 1e-8f;
        float l21 = sqrtf(sq1);

        // Output rows slab*128 + l0, l0+1 => 6 contiguous floats.
        float* o = out + ((size_t)slab * LL + l0) * 3;
        o[0] = cos0;
        o[1] = l20;
        o[2] = tl10;
        o[3] = cos1;
        o[4] = l21;
        o[5] = tl11;
    }
}

extern "C" void kernel_launch(void* const* d_in, const int* in_sizes, int n_in,
                              void* d_out, int out_size)
{
    const float* x = (const float*)d_in[0];
    const float* y = (const float*)d_in[1];
    float* out = (float*)d_out;

    dim3 grid(NBLOCKS);     // 4096 blocks
    dim3 block(THREADS);    // 64 threads = 2 warps
    hcmp_kernel<<<grid, block>>>(x, y, out);
}